// round 8
// baseline (speedup 1.0000x reference)
#include <cuda_runtime.h>
#include <cuda_bf16.h>
#include <cstdint>

#define NN   256
#define NE   1024
#define MAXC 64
#define WINF (1<<20)
#define NT   256       // threads per block
#define FCP  4         // FC1 k-pieces per input

typedef unsigned long long ull;
union F2U { float2 f; ull u; };

// ---------------- resettable state (ONE memset per replay) ----------------
struct __align__(16) Flags {
    float hidden[128 * 200];   // FC1 atomic accumulators (needs zero)
    int   done[NN * 64];       // (neuron, batch-pair) completion flags
    int   hcnt[2];             // FC1 task counters per 64-batch half
    int   sched_ready;
};
__device__ Flags g_flags;

// ---------------- persistent scratch (rewritten before use) ----------------
__device__ float g_act[(size_t)NN * 128 * 784];   // [n][b][p]
__device__ int   g_fin[NN * MAXC];
__device__ int   g_fcc[NN * MAXC];
__device__ int   g_fdeg[NN];
__device__ int   g_order[NN];
__device__ int   g_total;          // # needed conv neurons (excl 0, 255)
__device__ int   g_fc1target;

#define FMA2(d, a, b) \
    asm("fma.rn.f32x2 %0, %1, %2, %0;" : "+l"(d) : "l"(a), "l"(b))

__device__ __forceinline__ int ldacq(const int* p) {
    int v; asm volatile("ld.acquire.gpu.global.b32 %0, [%1];" : "=r"(v) : "l"(p) : "memory");
    return v;
}
__device__ __forceinline__ void strel(int* p, int v) {
    asm volatile("st.release.gpu.global.b32 [%0], %1;" :: "l"(p), "r"(v) : "memory");
}
__device__ __forceinline__ void spinf(const int* p) {        // tight
    if (ldacq(p)) return;
    while (!ldacq(p)) __nanosleep(20);
}
__device__ __forceinline__ void spinb(const int* p) {        // backoff (FC gates)
    if (ldacq(p)) return;
    int d = 128;
    while (!ldacq(p)) { __nanosleep(d); if (d < 1024) d <<= 1; }
}

// ---------------- shared memory union ----------------
struct SchedSM { int src[NE], tgt[NE], wave[NN], need[NN], list[NN]; int chg, cnt; };
struct ConvSM  { ull img[2][1056]; ull wk2[18 * 25]; };
struct FCSM    { float w[16][72]; float2 a[16][66]; };
union  SMU { SchedSM sch; ConvSM cv; FCSM fc; };

// stage one channel (2 batches packed in ull) — conflict-free STS.64
__device__ __forceinline__ void stage2(ull* imgU, const float* sp, int tid) {
    if (tid < 196) {
        const int col  = tid % 28;
        const int rowg = tid / 28;
        const float* p0 = sp + rowg * 4 * 28 + col;
        const float* p1 = p0 + 784;
        ull* d = imgU + (rowg * 4 + 2) * 33 + col + 2;
#pragma unroll
        for (int r = 0; r < 4; ++r) {
            F2U u; u.f = make_float2(__ldg(p0 + r * 28), __ldg(p1 + r * 28));
            d[r * 33] = u.u;
        }
    }
}

// 4px x 2batch packed conv
__device__ __forceinline__ void conv4(const ull* imb, const ull* w2, ull acc[4]) {
#pragma unroll
    for (int dy = 0; dy < 5; ++dy) {
        const ull* rp = imb + dy * 33;
        ull v[8];
#pragma unroll
        for (int j = 0; j < 8; ++j) v[j] = rp[j];
#pragma unroll
        for (int dx = 0; dx < 5; ++dx) {
            ull wv = w2[dy * 5 + dx];
#pragma unroll
            for (int o = 0; o < 4; ++o) FMA2(acc[o], wv, v[dx + o]);
        }
    }
}

__device__ __forceinline__ void store4(ull acc[4], float* d0) {
    F2U u0, u1, u2, u3;
    u0.u = acc[0]; u1.u = acc[1]; u2.u = acc[2]; u3.u = acc[3];
    float4 o0 = make_float4(fmaxf(u0.f.x, 0.f), fmaxf(u1.f.x, 0.f),
                            fmaxf(u2.f.x, 0.f), fmaxf(u3.f.x, 0.f));
    float4 o1 = make_float4(fmaxf(u0.f.y, 0.f), fmaxf(u1.f.y, 0.f),
                            fmaxf(u2.f.y, 0.f), fmaxf(u3.f.y, 0.f));
    *(float4*)d0         = o0;
    *(float4*)(d0 + 784) = o1;
}

// =====================================================================
// single persistent kernel: sched | 64 conv lanes (+FC2) | FC1 blocks
// =====================================================================
__global__ void __launch_bounds__(NT) net_kernel(
    const float* __restrict__ x,
    const int* __restrict__ src, const int* __restrict__ tgt,
    const float* __restrict__ conv_w, const float* __restrict__ conv_b,
    const float* __restrict__ fc1_w,  const float* __restrict__ fc1_b,
    const float* __restrict__ fc2_w,  const float* __restrict__ fc2_b,
    float* __restrict__ out, int cmax, int fcK, int nb)
{
    __shared__ SMU sm;
    const int tid = threadIdx.x;
    const int bid = blockIdx.x;

    // ================= block 0: scheduler only =================
    if (bid == 0) {
        for (int i = tid; i < NE; i += NT) { sm.sch.src[i] = src[i]; sm.sch.tgt[i] = tgt[i]; }
        for (int i = tid; i < NN; i += NT) { sm.sch.wave[i] = (i == 0) ? 0 : WINF; sm.sch.need[i] = 0; }
        if (tid == 0) { sm.sch.chg = 0; sm.sch.cnt = 0; }
        __syncthreads();

        for (int pass = 0; pass < 300; ++pass) {
            for (int e = tid; e < NE; e += NT) {
                int ws = sm.sch.wave[sm.sch.src[e]];
                if (ws + 1 < sm.sch.wave[sm.sch.tgt[e]]) {
                    atomicMin(&sm.sch.wave[sm.sch.tgt[e]], ws + 1); sm.sch.chg = 1;
                }
            }
            __syncthreads();
            int c = sm.sch.chg; __syncthreads();
            if (tid == 0) sm.sch.chg = 0;
            __syncthreads();
            if (!c) break;
        }

        if (tid == 0) sm.sch.need[255] = 1;
        __syncthreads();
        for (int pass = 0; pass < 300; ++pass) {
            for (int e = tid; e < NE; e += NT) {
                int s = sm.sch.src[e], t = sm.sch.tgt[e];
                if (sm.sch.need[t] && sm.sch.wave[s] < sm.sch.wave[t] && !sm.sch.need[s]) {
                    sm.sch.need[s] = 1; sm.sch.chg = 1;
                }
            }
            __syncthreads();
            int c = sm.sch.chg; __syncthreads();
            if (tid == 0) sm.sch.chg = 0;
            __syncthreads();
            if (!c) break;
        }

        for (int n = tid; n < NN; n += NT) {
            if (n != 0 && n != 255 && sm.sch.need[n]) {
                int r = 0;
                for (int m = 1; m < NN - 1; ++m)
                    if (sm.sch.need[m] && (sm.sch.wave[m] < sm.sch.wave[n] ||
                        (sm.sch.wave[m] == sm.sch.wave[n] && m < n))) r++;
                sm.sch.list[r] = n;
                atomicAdd(&sm.sch.cnt, 1);
            }
        }
        __syncthreads();
        const int total = sm.sch.cnt;

        {   // filtered in-lists via warp ballots (fcc = original channel rank)
            const int w8 = tid >> 5, lane = tid & 31;
            for (int ni = w8; ni <= total; ni += 8) {
                int n  = (ni == total) ? 255 : sm.sch.list[ni];
                int wn = sm.sch.wave[n];
                int cbase = 0, cnt = 0;
                for (int ch = 0; ch < NE; ch += 32) {
                    int e = ch + lane;
                    int te = sm.sch.tgt[e], se = sm.sch.src[e];
                    unsigned m_all  = __ballot_sync(0xffffffffu, te == n);
                    unsigned m_keep = __ballot_sync(0xffffffffu, te == n && sm.sch.wave[se] < wn);
                    if (m_keep & (1u << lane)) {
                        int c   = cbase + __popc(m_all  & ((1u << lane) - 1));
                        int pos = cnt   + __popc(m_keep & ((1u << lane) - 1));
                        if (pos < MAXC) { g_fin[n * MAXC + pos] = se; g_fcc[n * MAXC + pos] = c; }
                    }
                    cbase += __popc(m_all);
                    cnt   += __popc(m_keep);
                }
                if (lane == 0) g_fdeg[n] = cnt < MAXC ? cnt : MAXC;
            }
        }
        __syncthreads();
        for (int i = tid; i < total; i += NT) g_order[i] = sm.sch.list[i];
        __syncthreads();
        if (tid == 0) {
            g_total = total;
            g_fc1target = 4 * g_fdeg[255] * FCP;
            __threadfence();
            strel(&g_flags.sched_ready, 1);
        }
        return;
    }

    // ================= conv lane blocks: bid 1..64, pb = bid-1 =================
    if (bid <= 64) {
        const int pb = bid - 1;
        for (int i = tid; i < 2 * 1056; i += NT) ((ull*)sm.cv.img)[i] = 0ull;
        const int yy  = tid / 7;
        const int xx0 = (tid % 7) * 4;
        __syncthreads();

        // ---- neuron 0 from x (no schedule needed) ----
        {
            if (tid < 25) { F2U u; float w = conv_w[tid]; u.f = make_float2(w, w); sm.cv.wk2[tid] = u.u; }
            stage2(sm.cv.img[0], x + (size_t)pb * 1568, tid);
            __syncthreads();
            if (tid < 196) {
                ull acc[4];
                F2U b2; float b = conv_b[0]; b2.f = make_float2(b, b);
#pragma unroll
                for (int o = 0; o < 4; ++o) acc[o] = b2.u;
                conv4(sm.cv.img[0] + yy * 33 + xx0, sm.cv.wk2, acc);
                store4(acc, g_act + (size_t)(pb * 2) * 784 + yy * 28 + xx0);
            }
            __syncthreads();
            if (tid == 0) { __threadfence(); strel(&g_flags.done[pb], 1); }
        }

        // ---- wait for schedule ----
        if (tid == 0) spinf(&g_flags.sched_ready);
        __syncthreads();
        const int total = g_total;

        // ---- walk all needed neurons in wave-major order (flag-free) ----
        for (int i = 0; i < total; ++i) {
            const int n = g_order[i];
            const int C = g_fdeg[n];
            const int* fin = g_fin + n * MAXC;
            const int* fcc = g_fcc + n * MAXC;
            const float* wbase = conv_w + (size_t)n * cmax * 25;

            const int CW = C < 16 ? C : 16;
            for (int q = tid; q < CW * 25; q += NT) {
                int c = q / 25, r = q - c * 25;
                F2U u; float w = wbase[fcc[c] * 25 + r];
                u.f = make_float2(w, w);
                sm.cv.wk2[c * 25 + r] = u.u;
            }
            if (C > 0)
                stage2(sm.cv.img[0], g_act + ((size_t)fin[0] * 128 + pb * 2) * 784, tid);
            __syncthreads();

            ull acc[4];
            { F2U b2; float b = conv_b[n]; b2.f = make_float2(b, b);
#pragma unroll
              for (int o = 0; o < 4; ++o) acc[o] = b2.u; }

            for (int c = 0; c < C; ++c) {
                const int buf = c & 1;
                if (c + 1 < C) {
                    stage2(sm.cv.img[buf ^ 1],
                           g_act + ((size_t)fin[c + 1] * 128 + pb * 2) * 784, tid);
                    if (c + 1 >= 16 && tid < 25) {
                        F2U u; float w = wbase[fcc[c + 1] * 25 + tid];
                        u.f = make_float2(w, w);
                        sm.cv.wk2[(16 + ((c + 1) & 1)) * 25 + tid] = u.u;
                    }
                }
                if (tid < 196) {
                    const ull* w2 = sm.cv.wk2 + ((c < 16) ? c : (16 + (c & 1))) * 25;
                    conv4(sm.cv.img[buf] + yy * 33 + xx0, w2, acc);
                }
                __syncthreads();
            }
            if (tid < 196)
                store4(acc, g_act + ((size_t)n * 128 + pb * 2) * 784 + yy * 28 + xx0);
            __syncthreads();
            if (tid == 0) { __threadfence(); strel(&g_flags.done[n * 64 + pb], 1); }
        }

        // ---- FC2 + log_softmax on lane blocks 1..16 (8 warps = 8 batches each) ----
        if (bid <= 16) {
            const int lane   = tid & 31;
            const int b      = (bid - 1) * 8 + (tid >> 5);
            const int target = g_fc1target;
            if (lane == 0) {
                const int* cc = &g_flags.hcnt[b >> 6];
                while (ldacq(cc) < target) __nanosleep(256);
            }
            __syncwarp();
            float acc = 0.f;
            if (lane < 10) {
                acc = fc2_b[lane];
                const float* wp = fc2_w + lane * 200;
                const float* hp = g_flags.hidden + b * 200;
#pragma unroll 5
                for (int h4 = 0; h4 < 50; ++h4) {
                    float4 w  = ((const float4*)wp)[h4];
                    float4 hv = ((const float4*)hp)[h4];
                    float4 fb = ((const float4*)fc1_b)[h4];
                    acc += fmaxf(hv.x + fb.x, 0.f) * w.x + fmaxf(hv.y + fb.y, 0.f) * w.y
                         + fmaxf(hv.z + fb.z, 0.f) * w.z + fmaxf(hv.w + fb.w, 0.f) * w.w;
                }
            }
            float m = (lane < 10) ? acc : -1e30f;
#pragma unroll
            for (int off = 16; off; off >>= 1) m = fmaxf(m, __shfl_xor_sync(0xffffffffu, m, off));
            float e = (lane < 10) ? expf(acc - m) : 0.f;
            float s = e;
#pragma unroll
            for (int off = 16; off; off >>= 1) s += __shfl_xor_sync(0xffffffffu, s, off);
            const float lse = m + logf(s);
            if (lane < 10) out[b * 10 + lane] = acc - lse;
        }
        return;
    }

    // ================= FC1 blocks: bid >= 65 =================
    {
        if (tid == 0) spinf(&g_flags.sched_ready);
        __syncthreads();
        const int fdeg255 = g_fdeg[255];
        const int ntF = 8 * fdeg255 * FCP;
        const int* fin = g_fin + 255 * MAXC;
        const int* fcc = g_fcc + 255 * MAXC;
        const int hg = tid >> 5;
        const int bg = tid & 31;

        for (int t = bid - 65; t < ntF; t += nb - 65) {
            const int tile = t & 7;
            const int rest = t >> 3;
            const int c    = rest % fdeg255;
            const int pc   = rest / fdeg255;
            const int h0   = (tile >> 1) * 64;
            const int b0   = (tile & 1) * 64;
            const int kq0  = (pc * 49) / FCP;
            const int kq1  = ((pc + 1) * 49) / FCP;

            if (tid < 32) spinb(&g_flags.done[fin[c] * 64 + (b0 >> 1) + tid]);
            __syncthreads();

            ull acc[4][2];
#pragma unroll
            for (int i = 0; i < 4; ++i) { acc[i][0] = 0ull; acc[i][1] = 0ull; }

            const float* wrow0 = fc1_w + (size_t)fcc[c] * 784;
            const float* arow0 = g_act + ((size_t)fin[c] * 128 + b0) * 784;
            const int row = tid >> 2, c4 = tid & 3;

            for (int kq = kq0; kq < kq1; ++kq) {
                const int p0 = kq * 16;
                {   // stage weights 64h x 16k
                    int h = h0 + row;
                    float4 v = (h < 200) ? *(const float4*)(wrow0 + (size_t)h * fcK + p0 + c4 * 4)
                                         : make_float4(0.f, 0.f, 0.f, 0.f);
                    sm.fc.w[c4 * 4 + 0][row] = v.x; sm.fc.w[c4 * 4 + 1][row] = v.y;
                    sm.fc.w[c4 * 4 + 2][row] = v.z; sm.fc.w[c4 * 4 + 3][row] = v.w;
                }
                {   // stage acts 64b x 16k (dup-packed)
                    float4 v = *(const float4*)(arow0 + (size_t)row * 784 + p0 + c4 * 4);
                    sm.fc.a[c4 * 4 + 0][row] = make_float2(v.x, v.x);
                    sm.fc.a[c4 * 4 + 1][row] = make_float2(v.y, v.y);
                    sm.fc.a[c4 * 4 + 2][row] = make_float2(v.z, v.z);
                    sm.fc.a[c4 * 4 + 3][row] = make_float2(v.w, v.w);
                }
                __syncthreads();
#pragma unroll
                for (int k = 0; k < 16; ++k) {
                    const ull* wp = (const ull*)&sm.fc.w[k][hg * 8];
                    const ull* ap = (const ull*)&sm.fc.a[k][bg * 2];
                    ull w0 = wp[0], w1 = wp[1], w2v = wp[2], w3 = wp[3];
                    ull a0 = ap[0], a1 = ap[1];
                    FMA2(acc[0][0], w0,  a0); FMA2(acc[0][1], w0,  a1);
                    FMA2(acc[1][0], w1,  a0); FMA2(acc[1][1], w1,  a1);
                    FMA2(acc[2][0], w2v, a0); FMA2(acc[2][1], w2v, a1);
                    FMA2(acc[3][0], w3,  a0); FMA2(acc[3][1], w3,  a1);
                }
                __syncthreads();
            }
#pragma unroll
            for (int i = 0; i < 4; ++i) {
                const int h = h0 + hg * 8 + i * 2;
                if (h < 200) {
#pragma unroll
                    for (int j = 0; j < 2; ++j) {
                        F2U u; u.u = acc[i][j];
                        const int b = b0 + bg * 2 + j;
                        atomicAdd((float2*)&g_flags.hidden[b * 200 + h], u.f);
                    }
                }
            }
            __syncthreads();
            if (tid == 0) { __threadfence(); atomicAdd(&g_flags.hcnt[b0 >> 6], 1); }
        }
    }
}

// ---------------- launch: ONE memset + ONE kernel ----------------
extern "C" void kernel_launch(void* const* d_in, const int* in_sizes, int n_in,
                              void* d_out, int out_size) {
    const float* x      = (const float*)d_in[0];
    const int*   src    = (const int*)  d_in[1];
    const int*   tgt    = (const int*)  d_in[2];
    const float* conv_w = (const float*)d_in[3];
    const float* conv_b = (const float*)d_in[4];
    const float* fc1_w  = (const float*)d_in[5];
    const float* fc1_b  = (const float*)d_in[6];
    const float* fc2_w  = (const float*)d_in[7];
    const float* fc2_b  = (const float*)d_in[8];

    const int cmax = in_sizes[3] / (NN * 25);
    const int fcK  = in_sizes[5] / 200;

    void* flagsPtr = nullptr;
    cudaGetSymbolAddress(&flagsPtr, g_flags);
    cudaMemsetAsync(flagsPtr, 0, sizeof(Flags), 0);

    int dev = 0, sms = 0, occ = 0;
    cudaGetDevice(&dev);
    cudaDeviceGetAttribute(&sms, cudaDevAttrMultiProcessorCount, dev);
    cudaOccupancyMaxActiveBlocksPerMultiprocessor(&occ, net_kernel, NT, 0);
    int nb = sms * occ;
    if (nb < 128) nb = 128;

    net_kernel<<<nb, NT>>>(x, src, tgt, conv_w, conv_b, fc1_w, fc1_b,
                           fc2_w, fc2_b, (float*)d_out, cmax, fcK, nb);
}

// round 9
// speedup vs baseline: 1.0923x; 1.0923x over previous
#include <cuda_runtime.h>
#include <cuda_bf16.h>
#include <cstdint>

#define NN    256
#define NE    1024
#define MAXC  64
#define WINF  (1<<20)
#define NT    256
#define FCP   8          // FC1 k-pieces per input
#define NSLOT 24         // smem image slots for neurons (0..23); 24 = scratch
#define WCAP  64         // packed weight-pool capacity (channels)

typedef unsigned long long ull;
union F2U { float2 f; ull u; };

// dynamic smem: 25 images + weight pool + fallback weight buf
#define IMG_ULL   1056                       // 32 rows x 33 ull
#define SMEM_BYTES ((NSLOT + 1) * IMG_ULL * 8 + WCAP * 25 * 8 + 32 * 8)

// ---------------- resettable state (ONE memset per replay) ----------------
struct __align__(16) Flags {
    float hidden[128 * 200];
    int   done[NN * 64];
    int   hcnt[2];
    int   sched_ready;
};
__device__ Flags g_flags;

// ---------------- persistent scratch (rewritten by scheduler each replay) ----
__device__ float g_act[(size_t)NN * 128 * 784];
__device__ int   g_fin[NN * MAXC];
__device__ int   g_fcc[NN * MAXC];
__device__ int   g_fdeg[NN];
__device__ int   g_order[NN];
__device__ int   g_slot[NN];       // smem slot per neuron, -1 = none
__device__ int   g_is255in[NN];    // neuron is an input of 255
__device__ int   g_wsrc[WCAP];     // packed channel -> global weight-channel idx
__device__ int   g_wboff[NN];      // per order-index: pool offset or -1
__device__ int   g_wtot;
__device__ int   g_total;
__device__ int   g_fc1target;

#define FMA2(d, a, b) \
    asm("fma.rn.f32x2 %0, %1, %2, %0;" : "+l"(d) : "l"(a), "l"(b))

__device__ __forceinline__ int ldacq(const int* p) {
    int v; asm volatile("ld.acquire.gpu.global.b32 %0, [%1];" : "=r"(v) : "l"(p) : "memory");
    return v;
}
__device__ __forceinline__ void strel(int* p, int v) {
    asm volatile("st.release.gpu.global.b32 [%0], %1;" :: "l"(p), "r"(v) : "memory");
}
__device__ __forceinline__ void spinf(const int* p) {
    if (ldacq(p)) return;
    while (!ldacq(p)) __nanosleep(20);
}
__device__ __forceinline__ void spinb(const int* p) {
    if (ldacq(p)) return;
    int d = 128;
    while (!ldacq(p)) { __nanosleep(d); if (d < 1024) d <<= 1; }
}

struct SchedSM { int src[NE], tgt[NE], wave[NN], need[NN], list[NN]; int chg, cnt; };
struct FCSM    { float w[16][72]; float2 a[16][66]; };

// stage one channel (2 batches packed) into an image slot — conflict-free STS.64
__device__ __forceinline__ void stage2(ull* imgU, const float* sp, int tid) {
    if (tid < 196) {
        const int col  = tid % 28;
        const int rowg = tid / 28;
        const float* p0 = sp + rowg * 4 * 28 + col;
        const float* p1 = p0 + 784;
        ull* d = imgU + (rowg * 4 + 2) * 33 + col + 2;
#pragma unroll
        for (int r = 0; r < 4; ++r) {
            F2U u; u.f = make_float2(__ldg(p0 + r * 28), __ldg(p1 + r * 28));
            d[r * 33] = u.u;
        }
    }
}

// 4px x 2batch packed conv
__device__ __forceinline__ void conv4(const ull* imb, const ull* w2, ull acc[4]) {
#pragma unroll
    for (int dy = 0; dy < 5; ++dy) {
        const ull* rp = imb + dy * 33;
        ull v[8];
#pragma unroll
        for (int j = 0; j < 8; ++j) v[j] = rp[j];
#pragma unroll
        for (int dx = 0; dx < 5; ++dx) {
            ull wv = w2[dy * 5 + dx];
#pragma unroll
            for (int o = 0; o < 4; ++o) FMA2(acc[o], wv, v[dx + o]);
        }
    }
}

// relu + write to own smem slot, optionally also to g_act
__device__ __forceinline__ void emit4(ull acc[4], ull* sdst, float* gdst,
                                      int yy, int xx0) {
    F2U r[4];
#pragma unroll
    for (int o = 0; o < 4; ++o) {
        F2U u; u.u = acc[o];
        r[o].f = make_float2(fmaxf(u.f.x, 0.f), fmaxf(u.f.y, 0.f));
    }
    if (sdst) {
        ull* d = sdst + (yy + 2) * 33 + xx0 + 2;
#pragma unroll
        for (int o = 0; o < 4; ++o) d[o] = r[o].u;
    }
    if (gdst) {
        float* d0 = gdst + yy * 28 + xx0;
        *(float4*)d0         = make_float4(r[0].f.x, r[1].f.x, r[2].f.x, r[3].f.x);
        *(float4*)(d0 + 784) = make_float4(r[0].f.y, r[1].f.y, r[2].f.y, r[3].f.y);
    }
}

// =====================================================================
// single persistent kernel: sched(0) | lanes(1..64, +FC2 on 1..16) | FC1(65+)
// =====================================================================
__global__ void __launch_bounds__(NT) net_kernel(
    const float* __restrict__ x,
    const int* __restrict__ src, const int* __restrict__ tgt,
    const float* __restrict__ conv_w, const float* __restrict__ conv_b,
    const float* __restrict__ fc1_w,  const float* __restrict__ fc1_b,
    const float* __restrict__ fc2_w,  const float* __restrict__ fc2_b,
    float* __restrict__ out, int cmax, int fcK, int nb)
{
    extern __shared__ __align__(16) char dynsm[];
    const int tid = threadIdx.x;
    const int bid = blockIdx.x;

    // ================= block 0: scheduler =================
    if (bid == 0) {
        SchedSM* sch = (SchedSM*)dynsm;
        for (int i = tid; i < NE; i += NT) { sch->src[i] = src[i]; sch->tgt[i] = tgt[i]; }
        for (int i = tid; i < NN; i += NT) {
            sch->wave[i] = (i == 0) ? 0 : WINF; sch->need[i] = 0;
            g_slot[i] = -1; g_is255in[i] = 0;
        }
        if (tid == 0) { sch->chg = 0; sch->cnt = 0; g_slot[0] = 0; }
        __syncthreads();

        for (int pass = 0; pass < 300; ++pass) {
            for (int e = tid; e < NE; e += NT) {
                int ws = sch->wave[sch->src[e]];
                if (ws + 1 < sch->wave[sch->tgt[e]]) {
                    atomicMin(&sch->wave[sch->tgt[e]], ws + 1); sch->chg = 1;
                }
            }
            __syncthreads();
            int c = sch->chg; __syncthreads();
            if (tid == 0) sch->chg = 0;
            __syncthreads();
            if (!c) break;
        }

        if (tid == 0) sch->need[255] = 1;
        __syncthreads();
        for (int pass = 0; pass < 300; ++pass) {
            for (int e = tid; e < NE; e += NT) {
                int s = sch->src[e], t = sch->tgt[e];
                if (sch->need[t] && sch->wave[s] < sch->wave[t] && !sch->need[s]) {
                    sch->need[s] = 1; sch->chg = 1;
                }
            }
            __syncthreads();
            int c = sch->chg; __syncthreads();
            if (tid == 0) sch->chg = 0;
            __syncthreads();
            if (!c) break;
        }

        for (int n = tid; n < NN; n += NT) {
            if (n != 0 && n != 255 && sch->need[n]) {
                int r = 0;
                for (int m = 1; m < NN - 1; ++m)
                    if (sch->need[m] && (sch->wave[m] < sch->wave[n] ||
                        (sch->wave[m] == sch->wave[n] && m < n))) r++;
                sch->list[r] = n;
                atomicAdd(&sch->cnt, 1);
            }
        }
        __syncthreads();
        const int total = sch->cnt;

        {   // filtered in-lists via warp ballots
            const int w8 = tid >> 5, lane = tid & 31;
            for (int ni = w8; ni <= total; ni += 8) {
                int n  = (ni == total) ? 255 : sch->list[ni];
                int wn = sch->wave[n];
                int cbase = 0, cnt = 0;
                for (int ch = 0; ch < NE; ch += 32) {
                    int e = ch + lane;
                    int te = sch->tgt[e], se = sch->src[e];
                    unsigned m_all  = __ballot_sync(0xffffffffu, te == n);
                    unsigned m_keep = __ballot_sync(0xffffffffu, te == n && sch->wave[se] < wn);
                    if (m_keep & (1u << lane)) {
                        int c   = cbase + __popc(m_all  & ((1u << lane) - 1));
                        int pos = cnt   + __popc(m_keep & ((1u << lane) - 1));
                        if (pos < MAXC) { g_fin[n * MAXC + pos] = se; g_fcc[n * MAXC + pos] = c; }
                    }
                    cbase += __popc(m_all);
                    cnt   += __popc(m_keep);
                }
                if (lane == 0) g_fdeg[n] = cnt < MAXC ? cnt : MAXC;
            }
        }
        __syncthreads();
        for (int k = tid; k < g_fdeg[255]; k += NT) g_is255in[g_fin[255 * MAXC + k]] = 1;
        for (int i = tid; i < total; i += NT) g_order[i] = sch->list[i];
        __syncthreads();

        if (tid == 0) {   // slots + packed weight pool
            int off = 0;
            for (int i = 0; i < total; ++i) {
                int n = g_order[i];
                g_slot[n] = (i + 1 < NSLOT) ? (i + 1) : -1;
                int C = g_fdeg[n];
                if (off + C <= WCAP) {
                    g_wboff[i] = off;
                    for (int c = 0; c < C; ++c)
                        g_wsrc[off + c] = n * cmax + g_fcc[n * MAXC + c];
                    off += C;
                } else g_wboff[i] = -1;
            }
            g_wtot = off;
            g_total = total;
            g_fc1target = 4 * g_fdeg[255] * FCP;
            __threadfence();
            strel(&g_flags.sched_ready, 1);
        }
        return;
    }

    // ================= conv lane blocks: bid 1..64 =================
    if (bid <= 64) {
        const int pb = bid - 1;
        ull* imgs  = (ull*)dynsm;
        ull* wpool = imgs + (NSLOT + 1) * IMG_ULL;
        ull* wk2   = wpool + WCAP * 25;
        ull* scr   = imgs + NSLOT * IMG_ULL;       // scratch slot

        for (int q = tid; q < (NSLOT + 1) * IMG_ULL; q += NT) imgs[q] = 0ull;
        const int yy  = tid / 7;
        const int xx0 = (tid % 7) * 4;
        __syncthreads();

        // ---- neuron 0 from x ----
        {
            if (tid < 25) { F2U u; float w = conv_w[tid]; u.f = make_float2(w, w); wk2[tid] = u.u; }
            stage2(scr, x + (size_t)pb * 1568, tid);
            __syncthreads();
            if (tid < 196) {
                ull acc[4];
                F2U b2; float b = conv_b[0]; b2.f = make_float2(b, b);
#pragma unroll
                for (int o = 0; o < 4; ++o) acc[o] = b2.u;
                conv4(scr + yy * 33 + xx0, wk2, acc);
                emit4(acc, imgs, g_act + (size_t)(pb * 2) * 784, yy, xx0);
            }
            __syncthreads();
            if (tid == 0) { __threadfence(); strel(&g_flags.done[pb], 1); }
        }

        // ---- wait for schedule, then bulk-load the weight pool ----
        if (tid == 0) spinf(&g_flags.sched_ready);
        __syncthreads();
        const int total = g_total;
        const int wtot  = g_wtot;
        for (int q = tid; q < wtot * 25; q += NT) {
            F2U u; float w = conv_w[(size_t)g_wsrc[q / 25] * 25 + (q % 25)];
            u.f = make_float2(w, w);
            wpool[q] = u.u;
        }
        __syncthreads();

        // ---- flag-free walk, activations resident in smem ----
        for (int i = 0; i < total; ++i) {
            const int n  = g_order[i];
            const int C  = g_fdeg[n];
            const int so = g_slot[n];
            const int wb = g_wboff[i];
            const int* fin = g_fin + n * MAXC;
            const int* fcc = g_fcc + n * MAXC;

            ull acc[4];
            { F2U b2; float b = conv_b[n]; b2.f = make_float2(b, b);
#pragma unroll
              for (int o = 0; o < 4; ++o) acc[o] = b2.u; }

            for (int c = 0; c < C; ++c) {
                const int in = fin[c];
                const int s  = g_slot[in];
                const ull* ip;
                if (s >= 0) ip = imgs + s * IMG_ULL;
                else {   // rare: input not smem-resident
                    __syncthreads();
                    stage2(scr, g_act + ((size_t)in * 128 + pb * 2) * 784, tid);
                    __syncthreads();
                    ip = scr;
                }
                const ull* wp;
                if (wb >= 0) wp = wpool + (wb + c) * 25;
                else {       // rare: weights beyond pool cap
                    __syncthreads();
                    if (tid < 25) {
                        F2U u; float w = conv_w[((size_t)n * cmax + fcc[c]) * 25 + tid];
                        u.f = make_float2(w, w);
                        wk2[tid] = u.u;
                    }
                    __syncthreads();
                    wp = wk2;
                }
                if (tid < 196) conv4(ip + yy * 33 + xx0, wp, acc);
            }
            const int pub = g_is255in[n];
            if (tid < 196)
                emit4(acc,
                      (so >= 0) ? imgs + so * IMG_ULL : nullptr,
                      (pub || so < 0) ? g_act + ((size_t)n * 128 + pb * 2) * 784 : nullptr,
                      yy, xx0);
            __syncthreads();
            if (pub && tid == 0) { __threadfence(); strel(&g_flags.done[n * 64 + pb], 1); }
        }

        // ---- FC2 + log_softmax on lane blocks 1..16 ----
        if (bid <= 16) {
            const int lane   = tid & 31;
            const int b      = (bid - 1) * 8 + (tid >> 5);
            const int target = g_fc1target;
            if (lane == 0) {
                const int* cc = &g_flags.hcnt[b >> 6];
                while (ldacq(cc) < target) __nanosleep(256);
            }
            __syncwarp();
            float acc = 0.f;
            if (lane < 10) {
                acc = fc2_b[lane];
                const float* wp = fc2_w + lane * 200;
                const float* hp = g_flags.hidden + b * 200;
#pragma unroll 5
                for (int h4 = 0; h4 < 50; ++h4) {
                    float4 w  = ((const float4*)wp)[h4];
                    float4 hv = ((const float4*)hp)[h4];
                    float4 fb = ((const float4*)fc1_b)[h4];
                    acc += fmaxf(hv.x + fb.x, 0.f) * w.x + fmaxf(hv.y + fb.y, 0.f) * w.y
                         + fmaxf(hv.z + fb.z, 0.f) * w.z + fmaxf(hv.w + fb.w, 0.f) * w.w;
                }
            }
            float m = (lane < 10) ? acc : -1e30f;
#pragma unroll
            for (int off = 16; off; off >>= 1) m = fmaxf(m, __shfl_xor_sync(0xffffffffu, m, off));
            float e = (lane < 10) ? expf(acc - m) : 0.f;
            float s = e;
#pragma unroll
            for (int off = 16; off; off >>= 1) s += __shfl_xor_sync(0xffffffffu, s, off);
            const float lse = m + logf(s);
            if (lane < 10) out[b * 10 + lane] = acc - lse;
        }
        return;
    }

    // ================= FC1 blocks: bid >= 65 =================
    {
        FCSM* fc = (FCSM*)dynsm;
        if (tid == 0) spinf(&g_flags.sched_ready);
        __syncthreads();
        const int fdeg255 = g_fdeg[255];
        const int ntF = 8 * fdeg255 * FCP;
        const int* fin = g_fin + 255 * MAXC;
        const int* fcc = g_fcc + 255 * MAXC;
        const int hg = tid >> 5;
        const int bg = tid & 31;

        for (int t = bid - 65; t < ntF; t += nb - 65) {
            const int tile = t & 7;
            const int rest = t >> 3;
            const int c    = rest % fdeg255;
            const int pc   = rest / fdeg255;
            const int h0   = (tile >> 1) * 64;
            const int b0   = (tile & 1) * 64;
            const int kq0  = (pc * 49) / FCP;
            const int kq1  = ((pc + 1) * 49) / FCP;

            if (tid < 32) spinb(&g_flags.done[fin[c] * 64 + (b0 >> 1) + tid]);
            __syncthreads();

            ull acc[4][2];
#pragma unroll
            for (int i = 0; i < 4; ++i) { acc[i][0] = 0ull; acc[i][1] = 0ull; }

            const float* wrow0 = fc1_w + (size_t)fcc[c] * 784;
            const float* arow0 = g_act + ((size_t)fin[c] * 128 + b0) * 784;
            const int row = tid >> 2, c4 = tid & 3;

            for (int kq = kq0; kq < kq1; ++kq) {
                const int p0 = kq * 16;
                {
                    int h = h0 + row;
                    float4 v = (h < 200) ? *(const float4*)(wrow0 + (size_t)h * fcK + p0 + c4 * 4)
                                         : make_float4(0.f, 0.f, 0.f, 0.f);
                    fc->w[c4 * 4 + 0][row] = v.x; fc->w[c4 * 4 + 1][row] = v.y;
                    fc->w[c4 * 4 + 2][row] = v.z; fc->w[c4 * 4 + 3][row] = v.w;
                }
                {
                    float4 v = *(const float4*)(arow0 + (size_t)row * 784 + p0 + c4 * 4);
                    fc->a[c4 * 4 + 0][row] = make_float2(v.x, v.x);
                    fc->a[c4 * 4 + 1][row] = make_float2(v.y, v.y);
                    fc->a[c4 * 4 + 2][row] = make_float2(v.z, v.z);
                    fc->a[c4 * 4 + 3][row] = make_float2(v.w, v.w);
                }
                __syncthreads();
#pragma unroll
                for (int k = 0; k < 16; ++k) {
                    const ull* wp = (const ull*)&fc->w[k][hg * 8];
                    const ull* ap = (const ull*)&fc->a[k][bg * 2];
                    ull w0 = wp[0], w1 = wp[1], w2v = wp[2], w3 = wp[3];
                    ull a0 = ap[0], a1 = ap[1];
                    FMA2(acc[0][0], w0,  a0); FMA2(acc[0][1], w0,  a1);
                    FMA2(acc[1][0], w1,  a0); FMA2(acc[1][1], w1,  a1);
                    FMA2(acc[2][0], w2v, a0); FMA2(acc[2][1], w2v, a1);
                    FMA2(acc[3][0], w3,  a0); FMA2(acc[3][1], w3,  a1);
                }
                __syncthreads();
            }
#pragma unroll
            for (int i = 0; i < 4; ++i) {
                const int h = h0 + hg * 8 + i * 2;
                if (h < 200) {
#pragma unroll
                    for (int j = 0; j < 2; ++j) {
                        F2U u; u.u = acc[i][j];
                        const int b = b0 + bg * 2 + j;
                        atomicAdd((float2*)&g_flags.hidden[b * 200 + h], u.f);
                    }
                }
            }
            __syncthreads();
            if (tid == 0) { __threadfence(); atomicAdd(&g_flags.hcnt[b0 >> 6], 1); }
        }
    }
}

// ---------------- launch: ONE memset + ONE kernel ----------------
extern "C" void kernel_launch(void* const* d_in, const int* in_sizes, int n_in,
                              void* d_out, int out_size) {
    const float* x      = (const float*)d_in[0];
    const int*   src    = (const int*)  d_in[1];
    const int*   tgt    = (const int*)  d_in[2];
    const float* conv_w = (const float*)d_in[3];
    const float* conv_b = (const float*)d_in[4];
    const float* fc1_w  = (const float*)d_in[5];
    const float* fc1_b  = (const float*)d_in[6];
    const float* fc2_w  = (const float*)d_in[7];
    const float* fc2_b  = (const float*)d_in[8];

    const int cmax = in_sizes[3] / (NN * 25);
    const int fcK  = in_sizes[5] / 200;

    void* flagsPtr = nullptr;
    cudaGetSymbolAddress(&flagsPtr, g_flags);
    cudaMemsetAsync(flagsPtr, 0, sizeof(Flags), 0);

    cudaFuncSetAttribute(net_kernel, cudaFuncAttributeMaxDynamicSharedMemorySize,
                         SMEM_BYTES);

    int dev = 0, sms = 0;
    cudaGetDevice(&dev);
    cudaDeviceGetAttribute(&sms, cudaDevAttrMultiProcessorCount, dev);
    int nb = sms;             // 1 block/SM (forced by smem) — all co-resident
    if (nb < 66) nb = 66;

    net_kernel<<<nb, NT, SMEM_BYTES>>>(x, src, tgt, conv_w, conv_b, fc1_w, fc1_b,
                                       fc2_w, fc2_b, (float*)d_out, cmax, fcK, nb);
}

// round 10
// speedup vs baseline: 1.2523x; 1.1465x over previous
#include <cuda_runtime.h>
#include <cuda_bf16.h>
#include <cstdint>

#define NN    256
#define NE    1024
#define MAXC  64
#define WINF  (1<<20)
#define NSLOT 24
#define WCAP  64

typedef unsigned long long ull;
union F2U { float2 f; ull u; };

#define IMG_ULL    1056
#define CONV_SMEM  ((NSLOT + 1) * IMG_ULL * 8 + WCAP * 25 * 8 + 32 * 8)

// ---------------- device state ----------------
__device__ float g_hidden[128 * 200];             // zeroed by memset each replay
__device__ float g_act[(size_t)NN * 128 * 784];
__device__ int   g_fin[NN * MAXC];
__device__ int   g_fcc[NN * MAXC];
__device__ int   g_fdeg[NN];
__device__ int   g_order[NN];
__device__ int   g_slot[NN];
__device__ int   g_is255in[NN];
__device__ int   g_wsrc[WCAP];
__device__ int   g_wboff[NN];
__device__ int   g_wtot;
__device__ int   g_total;

#define FMA2(d, a, b) \
    asm("fma.rn.f32x2 %0, %1, %2, %0;" : "+l"(d) : "l"(a), "l"(b))

// =====================================================================
// K1: scheduler — 1 block, 1024 threads (1 edge per thread)
// =====================================================================
__global__ void __launch_bounds__(1024) sched_kernel(
    const int* __restrict__ src, const int* __restrict__ tgt, int cmax)
{
    __shared__ int s_src[NE], s_tgt[NE];
    __shared__ int s_wave[NN], s_need[NN], s_list[NN];
    __shared__ int s_chg, s_cnt;
    const int tid = threadIdx.x;

    s_src[tid] = src[tid];
    s_tgt[tid] = tgt[tid];
    if (tid < NN) {
        s_wave[tid] = (tid == 0) ? 0 : WINF;
        s_need[tid] = 0;
        g_slot[tid] = -1;
        g_is255in[tid] = 0;
    }
    if (tid == 0) { s_chg = 0; s_cnt = 0; g_slot[0] = 0; }
    __syncthreads();

    // BFS levels from 0 (edge-parallel, 1 edge/thread)
    for (int pass = 0; pass < 300; ++pass) {
        int ws = s_wave[s_src[tid]];
        if (ws + 1 < s_wave[s_tgt[tid]]) { atomicMin(&s_wave[s_tgt[tid]], ws + 1); s_chg = 1; }
        __syncthreads();
        int c = s_chg; __syncthreads();
        if (tid == 0) s_chg = 0;
        __syncthreads();
        if (!c) break;
    }

    // backward needed-set from 255 (strictly-decreasing-wave edges)
    if (tid == 0) s_need[255] = 1;
    __syncthreads();
    for (int pass = 0; pass < 300; ++pass) {
        int s = s_src[tid], t = s_tgt[tid];
        if (s_need[t] && s_wave[s] < s_wave[t] && !s_need[s]) { s_need[s] = 1; s_chg = 1; }
        __syncthreads();
        int c = s_chg; __syncthreads();
        if (tid == 0) s_chg = 0;
        __syncthreads();
        if (!c) break;
    }

    // wave-major rank of each needed conv neuron
    if (tid < NN && tid != 0 && tid != 255 && s_need[tid]) {
        int r = 0;
        for (int m = 1; m < NN - 1; ++m)
            if (s_need[m] && (s_wave[m] < s_wave[tid] ||
                (s_wave[m] == s_wave[tid] && m < tid))) r++;
        s_list[r] = tid;
        atomicAdd(&s_cnt, 1);
    }
    __syncthreads();
    const int total = s_cnt;

    // filtered in-lists via warp ballots (one neuron per warp round)
    {
        const int w = tid >> 5, lane = tid & 31;
        for (int ni = w; ni <= total; ni += 32) {
            int n  = (ni == total) ? 255 : s_list[ni];
            int wn = s_wave[n];
            int cbase = 0, cnt = 0;
            for (int ch = 0; ch < NE; ch += 32) {
                int e = ch + lane;
                int te = s_tgt[e], se = s_src[e];
                unsigned m_all  = __ballot_sync(0xffffffffu, te == n);
                unsigned m_keep = __ballot_sync(0xffffffffu, te == n && s_wave[se] < wn);
                if (m_keep & (1u << lane)) {
                    int c   = cbase + __popc(m_all  & ((1u << lane) - 1));
                    int pos = cnt   + __popc(m_keep & ((1u << lane) - 1));
                    if (pos < MAXC) { g_fin[n * MAXC + pos] = se; g_fcc[n * MAXC + pos] = c; }
                }
                cbase += __popc(m_all);
                cnt   += __popc(m_keep);
            }
            if (lane == 0) g_fdeg[n] = cnt < MAXC ? cnt : MAXC;
        }
    }
    __syncthreads();
    if (tid < NN) {
        if (tid < total) g_order[tid] = s_list[tid];
    }
    __syncthreads();
    for (int k = tid; k < g_fdeg[255]; k += 1024) g_is255in[g_fin[255 * MAXC + k]] = 1;

    if (tid == 0) {       // slots + packed weight-pool map
        int off = 0;
        for (int i = 0; i < total; ++i) {
            int n = s_list[i];
            g_slot[n] = (i + 1 < NSLOT) ? (i + 1) : -1;
            int C = g_fdeg[n];
            if (off + C <= WCAP) {
                g_wboff[i] = off;
                for (int c = 0; c < C; ++c)
                    g_wsrc[off + c] = n * cmax + g_fcc[n * MAXC + c];
                off += C;
            } else g_wboff[i] = -1;
        }
        g_wtot = off;
        g_total = total;
    }
}

// ---------------- conv helpers ----------------
__device__ __forceinline__ void stage2(ull* imgU, const float* sp, int tid) {
    if (tid < 196) {
        const int col  = tid % 28;
        const int rowg = tid / 28;
        const float* p0 = sp + rowg * 4 * 28 + col;
        const float* p1 = p0 + 784;
        ull* d = imgU + (rowg * 4 + 2) * 33 + col + 2;
#pragma unroll
        for (int r = 0; r < 4; ++r) {
            F2U u; u.f = make_float2(__ldg(p0 + r * 28), __ldg(p1 + r * 28));
            d[r * 33] = u.u;
        }
    }
}

__device__ __forceinline__ void conv4(const ull* imb, const ull* w2, ull acc[4]) {
#pragma unroll
    for (int dy = 0; dy < 5; ++dy) {
        const ull* rp = imb + dy * 33;
        ull v[8];
#pragma unroll
        for (int j = 0; j < 8; ++j) v[j] = rp[j];
#pragma unroll
        for (int dx = 0; dx < 5; ++dx) {
            ull wv = w2[dy * 5 + dx];
#pragma unroll
            for (int o = 0; o < 4; ++o) FMA2(acc[o], wv, v[dx + o]);
        }
    }
}

__device__ __forceinline__ void emit4(ull acc[4], ull* sdst, float* gdst,
                                      int yy, int xx0) {
    F2U r[4];
#pragma unroll
    for (int o = 0; o < 4; ++o) {
        F2U u; u.u = acc[o];
        r[o].f = make_float2(fmaxf(u.f.x, 0.f), fmaxf(u.f.y, 0.f));
    }
    if (sdst) {
        ull* d = sdst + (yy + 2) * 33 + xx0 + 2;
#pragma unroll
        for (int o = 0; o < 4; ++o) d[o] = r[o].u;
    }
    if (gdst) {
        float* d0 = gdst + yy * 28 + xx0;
        *(float4*)d0         = make_float4(r[0].f.x, r[1].f.x, r[2].f.x, r[3].f.x);
        *(float4*)(d0 + 784) = make_float4(r[0].f.y, r[1].f.y, r[2].f.y, r[3].f.y);
    }
}

// =====================================================================
// K2: conv lanes — 64 blocks, pb = blockIdx.x, flag-free smem walk
// =====================================================================
__global__ void __launch_bounds__(256) conv_kernel(
    const float* __restrict__ x,
    const float* __restrict__ conv_w, const float* __restrict__ conv_b,
    int cmax)
{
    extern __shared__ __align__(16) char dynsm[];
    const int tid = threadIdx.x;
    const int pb  = blockIdx.x;

    ull* imgs  = (ull*)dynsm;
    ull* wpool = imgs + (NSLOT + 1) * IMG_ULL;
    ull* wk2   = wpool + WCAP * 25;
    ull* scr   = imgs + NSLOT * IMG_ULL;

    for (int q = tid; q < (NSLOT + 1) * IMG_ULL; q += 256) imgs[q] = 0ull;
    const int yy  = tid / 7;
    const int xx0 = (tid % 7) * 4;

    // bulk-load packed weight pool (scheduler already done — stream order)
    const int total = g_total;
    const int wtot  = g_wtot;
    for (int q = tid; q < wtot * 25; q += 256) {
        F2U u; float w = __ldg(conv_w + (size_t)g_wsrc[q / 25] * 25 + (q % 25));
        u.f = make_float2(w, w);
        wpool[q] = u.u;
    }
    if (tid < 25) { F2U u; float w = conv_w[tid]; u.f = make_float2(w, w); wk2[tid] = u.u; }
    stage2(scr, x + (size_t)pb * 1568, tid);
    __syncthreads();

    // ---- neuron 0 ----
    if (tid < 196) {
        ull acc[4];
        F2U b2; float b = conv_b[0]; b2.f = make_float2(b, b);
#pragma unroll
        for (int o = 0; o < 4; ++o) acc[o] = b2.u;
        conv4(scr + yy * 33 + xx0, wk2, acc);
        emit4(acc, imgs, g_act + (size_t)(pb * 2) * 784, yy, xx0);
    }
    __syncthreads();

    // ---- flag-free walk ----
    for (int i = 0; i < total; ++i) {
        const int n  = g_order[i];
        const int C  = g_fdeg[n];
        const int so = g_slot[n];
        const int wb = g_wboff[i];
        const int* fin = g_fin + n * MAXC;
        const int* fcc = g_fcc + n * MAXC;

        ull acc[4];
        { F2U b2; float b = conv_b[n]; b2.f = make_float2(b, b);
#pragma unroll
          for (int o = 0; o < 4; ++o) acc[o] = b2.u; }

        for (int c = 0; c < C; ++c) {
            const int in = fin[c];
            const int s  = g_slot[in];
            const ull* ip;
            if (s >= 0) ip = imgs + s * IMG_ULL;
            else {
                __syncthreads();
                stage2(scr, g_act + ((size_t)in * 128 + pb * 2) * 784, tid);
                __syncthreads();
                ip = scr;
            }
            const ull* wp;
            if (wb >= 0) wp = wpool + (wb + c) * 25;
            else {
                __syncthreads();
                if (tid < 25) {
                    F2U u; float w = conv_w[((size_t)n * cmax + fcc[c]) * 25 + tid];
                    u.f = make_float2(w, w);
                    wk2[tid] = u.u;
                }
                __syncthreads();
                wp = wk2;
            }
            if (tid < 196) conv4(ip + yy * 33 + xx0, wp, acc);
        }
        const int pub = g_is255in[n];
        if (tid < 196)
            emit4(acc,
                  (so >= 0) ? imgs + so * IMG_ULL : nullptr,
                  (pub || so < 0) ? g_act + ((size_t)n * 128 + pb * 2) * 784 : nullptr,
                  yy, xx0);
        __syncthreads();
    }
}

// =====================================================================
// K3: FC1 — 128 blocks: 8 tiles(64h x 64b) x 16 k-splits, dbl-buffered
// =====================================================================
__global__ void __launch_bounds__(256) fc1_kernel(
    const float* __restrict__ fc1_w, int fcK)
{
    __shared__ __align__(16) float  s_w[16][72];
    __shared__ __align__(16) float2 s_a[16][66];

    const int tid  = threadIdx.x;
    const int tile = blockIdx.x >> 4;     // 0..7
    const int kc   = blockIdx.x & 15;     // 0..15
    const int h0   = (tile >> 1) * 64;
    const int b0   = (tile & 1) * 64;

    const int fdeg = g_fdeg[255];
    const int Kc   = fdeg * 49;
    const int* fin = g_fin + 255 * MAXC;
    const int* fcc = g_fcc + 255 * MAXC;

    const int hg  = tid >> 5;
    const int bg  = tid & 31;
    const int row = tid >> 2, c4 = tid & 3;
    const int h   = h0 + row;

    ull acc[4][2];
#pragma unroll
    for (int i = 0; i < 4; ++i) { acc[i][0] = 0ull; acc[i][1] = 0ull; }

    if (kc < Kc) {
        // prefetch first chunk
        float4 wreg = make_float4(0.f, 0.f, 0.f, 0.f), areg;
        {
            const int c = kc / 49, p0 = (kc % 49) * 16;
            if (h < 200)
                wreg = *(const float4*)(fc1_w + (size_t)fcc[c] * 784
                                        + (size_t)h * fcK + p0 + c4 * 4);
            areg = *(const float4*)(g_act + ((size_t)fin[c] * 128 + b0 + row) * 784
                                    + p0 + c4 * 4);
        }

        for (int kidx = kc; kidx < Kc; kidx += 16) {
            __syncthreads();
            s_w[c4 * 4 + 0][row] = wreg.x; s_w[c4 * 4 + 1][row] = wreg.y;
            s_w[c4 * 4 + 2][row] = wreg.z; s_w[c4 * 4 + 3][row] = wreg.w;
            s_a[c4 * 4 + 0][row] = make_float2(areg.x, areg.x);
            s_a[c4 * 4 + 1][row] = make_float2(areg.y, areg.y);
            s_a[c4 * 4 + 2][row] = make_float2(areg.z, areg.z);
            s_a[c4 * 4 + 3][row] = make_float2(areg.w, areg.w);

            const int nx = kidx + 16;
            if (nx < Kc) {       // prefetch next chunk while computing
                const int c = nx / 49, p0 = (nx % 49) * 16;
                if (h < 200)
                    wreg = *(const float4*)(fc1_w + (size_t)fcc[c] * 784
                                            + (size_t)h * fcK + p0 + c4 * 4);
                areg = *(const float4*)(g_act + ((size_t)fin[c] * 128 + b0 + row) * 784
                                        + p0 + c4 * 4);
            }
            __syncthreads();
#pragma unroll
            for (int k = 0; k < 16; ++k) {
                const ull* wp = (const ull*)&s_w[k][hg * 8];
                const ull* ap = (const ull*)&s_a[k][bg * 2];
                ull w0 = wp[0], w1 = wp[1], w2v = wp[2], w3 = wp[3];
                ull a0 = ap[0], a1 = ap[1];
                FMA2(acc[0][0], w0,  a0); FMA2(acc[0][1], w0,  a1);
                FMA2(acc[1][0], w1,  a0); FMA2(acc[1][1], w1,  a1);
                FMA2(acc[2][0], w2v, a0); FMA2(acc[2][1], w2v, a1);
                FMA2(acc[3][0], w3,  a0); FMA2(acc[3][1], w3,  a1);
            }
        }
#pragma unroll
        for (int i = 0; i < 4; ++i) {
            const int hh = h0 + hg * 8 + i * 2;
            if (hh < 200) {
#pragma unroll
                for (int j = 0; j < 2; ++j) {
                    F2U u; u.u = acc[i][j];
                    const int b = b0 + bg * 2 + j;
                    atomicAdd((float2*)&g_hidden[b * 200 + hh], u.f);
                }
            }
        }
    }
}

// =====================================================================
// K4: FC2 + log_softmax — 16 blocks x 8 warps (1 warp per batch row)
// =====================================================================
__global__ void __launch_bounds__(256) fc2_kernel(
    const float* __restrict__ fc1_b,
    const float* __restrict__ fc2_w, const float* __restrict__ fc2_b,
    float* __restrict__ out)
{
    const int lane = threadIdx.x & 31;
    const int b    = blockIdx.x * 8 + (threadIdx.x >> 5);

    float acc = 0.f;
    if (lane < 10) {
        acc = fc2_b[lane];
        const float* wp = fc2_w + lane * 200;
        const float* hp = g_hidden + b * 200;
#pragma unroll 5
        for (int h4 = 0; h4 < 50; ++h4) {
            float4 w  = ((const float4*)wp)[h4];
            float4 hv = ((const float4*)hp)[h4];
            float4 fb = ((const float4*)fc1_b)[h4];
            acc += fmaxf(hv.x + fb.x, 0.f) * w.x + fmaxf(hv.y + fb.y, 0.f) * w.y
                 + fmaxf(hv.z + fb.z, 0.f) * w.z + fmaxf(hv.w + fb.w, 0.f) * w.w;
        }
    }
    float m = (lane < 10) ? acc : -1e30f;
#pragma unroll
    for (int off = 16; off; off >>= 1) m = fmaxf(m, __shfl_xor_sync(0xffffffffu, m, off));
    float e = (lane < 10) ? expf(acc - m) : 0.f;
    float s = e;
#pragma unroll
    for (int off = 16; off; off >>= 1) s += __shfl_xor_sync(0xffffffffu, s, off);
    const float lse = m + logf(s);
    if (lane < 10) out[b * 10 + lane] = acc - lse;
}

// ---------------- launch: memset + 4 kernels, all stream-ordered ----------------
extern "C" void kernel_launch(void* const* d_in, const int* in_sizes, int n_in,
                              void* d_out, int out_size) {
    const float* x      = (const float*)d_in[0];
    const int*   src    = (const int*)  d_in[1];
    const int*   tgt    = (const int*)  d_in[2];
    const float* conv_w = (const float*)d_in[3];
    const float* conv_b = (const float*)d_in[4];
    const float* fc1_w  = (const float*)d_in[5];
    const float* fc1_b  = (const float*)d_in[6];
    const float* fc2_w  = (const float*)d_in[7];
    const float* fc2_b  = (const float*)d_in[8];

    const int cmax = in_sizes[3] / (NN * 25);
    const int fcK  = in_sizes[5] / 200;

    void* hidPtr = nullptr;
    cudaGetSymbolAddress(&hidPtr, g_hidden);
    cudaMemsetAsync(hidPtr, 0, 128 * 200 * sizeof(float), 0);

    cudaFuncSetAttribute(conv_kernel, cudaFuncAttributeMaxDynamicSharedMemorySize,
                         CONV_SMEM);

    sched_kernel<<<1, 1024>>>(src, tgt, cmax);
    conv_kernel<<<64, 256, CONV_SMEM>>>(x, conv_w, conv_b, cmax);
    fc1_kernel<<<128, 256>>>(fc1_w, fcK);
    fc2_kernel<<<16, 256>>>(fc1_b, fc2_w, fc2_b, (float*)d_out);
}